// round 12
// baseline (speedup 1.0000x reference)
#include <cuda_runtime.h>
#include <cuda_fp16.h>
#include <math.h>
#include <stdint.h>

// Problem constants
#define NTOT 8192   // B * A
#define BATCH 512
#define NADV 16
#define DIN 64      // DS + DO
#define HID 128

// Scratch
__device__ float g_x[NTOT * DIN];
__device__ float g_embp[4 * NTOT * HID];   // partial einsum sums (pre-tanh), 4 d-quarters
__device__ float g_vals[NTOT * HID];
__device__ float g_sc[NTOT];
// Hyper A tiles: fp16 hi only, pitch 272B; 128-row tile = 34816B = 2176 uint4
__device__ uint4 g_abf[64 * 2176];
// Tail tiles: fp16 hi/lo, pitch 528B; 128-row tile = 67584B = 4224 uint4
__device__ uint4 g_ebf[64 * 4224];   // emb tiles (tail A)
__device__ uint4 g_mbf[4 * 4224];    // mean tiles
__device__ uint4 g_wbf[5 * 4224];    // tail weights: vw1,vw2,aw1a,aw1b,aw2 ([k][n])
// Hyper B tiles: fp16 hi only, pitch 272B; tile = 34816B = 2176 uint4
__device__ uint4 g_bbf[64 * 2176];

// ---------------------------------------------------------------------------
// helpers
// ---------------------------------------------------------------------------
__device__ __forceinline__ uint32_t smem_u32(const void* p) {
    uint32_t a;
    asm("{ .reg .u64 t; cvta.to.shared.u64 t, %1; cvt.u32.u64 %0, t; }" : "=r"(a) : "l"(p));
    return a;
}
__device__ __forceinline__ void f2hl16(float v, uint16_t& h, uint16_t& l) {
    __half hh = __float2half_rn(v);
    float r = v - __half2float(hh);
    __half hl = __float2half_rn(r);
    h = __half_as_ushort(hh);
    l = __half_as_ushort(hl);
}
__device__ __forceinline__ void pack_hl2(float v0, float v1, uint32_t& hi, uint32_t& lo) {
    uint16_t h0, l0, h1, l1;
    f2hl16(v0, h0, l0);
    f2hl16(v1, h1, l1);
    hi = (uint32_t)h0 | ((uint32_t)h1 << 16);
    lo = (uint32_t)l0 | ((uint32_t)l1 << 16);
}
__device__ __forceinline__ uint32_t pack_h2(float v0, float v1) {
    return (uint32_t)__half_as_ushort(__float2half_rn(v0)) |
           ((uint32_t)__half_as_ushort(__float2half_rn(v1)) << 16);
}
__device__ __forceinline__ void ldsm_x4(uint32_t* r, uint32_t addr) {
    asm volatile("ldmatrix.sync.aligned.m8n8.x4.shared.b16 {%0,%1,%2,%3}, [%4];"
                 : "=r"(r[0]), "=r"(r[1]), "=r"(r[2]), "=r"(r[3]) : "r"(addr));
}
__device__ __forceinline__ void ldsm_x4_t(uint32_t* r, uint32_t addr) {
    asm volatile("ldmatrix.sync.aligned.m8n8.x4.trans.shared.b16 {%0,%1,%2,%3}, [%4];"
                 : "=r"(r[0]), "=r"(r[1]), "=r"(r[2]), "=r"(r[3]) : "r"(addr));
}
__device__ __forceinline__ void mma16816h(float* d, const uint32_t* a, uint32_t b0, uint32_t b1) {
    asm volatile(
        "mma.sync.aligned.m16n8k16.row.col.f32.f16.f16.f32 "
        "{%0,%1,%2,%3}, {%4,%5,%6,%7}, {%8,%9}, {%0,%1,%2,%3};"
        : "+f"(d[0]), "+f"(d[1]), "+f"(d[2]), "+f"(d[3])
        : "r"(a[0]), "r"(a[1]), "r"(a[2]), "r"(a[3]), "r"(b0), "r"(b1));
}
__device__ __forceinline__ void cp16(uint32_t dst, const void* src) {
    asm volatile("cp.async.cg.shared.global [%0], [%1], 16;" :: "r"(dst), "l"(src) : "memory");
}
#define CP_COMMIT() asm volatile("cp.async.commit_group;" ::: "memory")
#define CP_WAIT(N)  asm volatile("cp.async.wait_group %0;" :: "n"(N) : "memory")

// ---------------------------------------------------------------------------
// Kernel 0 (fused prep): blocks 0..511 h1 -> A tiles + g_x;
//   512..1023: hw2 -> B tiles;  1024..1063: tail weights -> g_wbf
// ---------------------------------------------------------------------------
__global__ __launch_bounds__(256) void k_prep(
    const float* __restrict__ obs, const float* __restrict__ lat,
    const float* __restrict__ hw1, const float* __restrict__ hb1,
    const float* __restrict__ hw2,
    const float* __restrict__ vw1, const float* __restrict__ vw2,
    const float* __restrict__ aw1, const float* __restrict__ aw2) {
    int tid = threadIdx.x;
    if (blockIdx.x >= 1024) {
        int idx = (blockIdx.x - 1024) * 256 + tid;  // 10240
        int t = idx >> 11, rem = idx & 2047;
        int k = rem >> 4, c = rem & 15;
        const float* W = (t == 0) ? vw1 : (t == 1) ? vw2 : (t == 2) ? aw1
                         : (t == 3) ? (aw1 + 16384) : aw2;
        uint32_t hi[4], lo[4];
#pragma unroll
        for (int j = 0; j < 4; j++) {
            float2 v = *(const float2*)(W + k * 128 + c * 8 + 2 * j);
            pack_hl2(v.x, v.y, hi[j], lo[j]);
        }
        uint8_t* base = (uint8_t*)g_wbf + t * 67584 + k * 528;
        *(uint4*)(base + c * 16) = make_uint4(hi[0], hi[1], hi[2], hi[3]);
        *(uint4*)(base + 256 + c * 16) = make_uint4(lo[0], lo[1], lo[2], lo[3]);
        return;
    }
    if (blockIdx.x >= 512) {
        int idx = (blockIdx.x - 512) * 256 + tid;   // 131072
        int n = idx & 127, kc = (idx >> 7) & 15, d = idx >> 11;
        int k0 = kc * 8;
        uint32_t hv[4];
#pragma unroll
        for (int j = 0; j < 4; j++) {
            float v0 = hw2[(k0 + 2 * j) * 8192 + d * 128 + n];
            float v1 = hw2[(k0 + 2 * j + 1) * 8192 + d * 128 + n];
            hv[j] = pack_h2(v0, v1);
        }
        uint8_t* base = (uint8_t*)g_bbf + d * 34816 + n * 272;
        *(uint4*)(base + k0 * 2) = make_uint4(hv[0], hv[1], hv[2], hv[3]);
        return;
    }
    // ---- build h1 ----
    __shared__ __align__(16) float sw[DIN][HID];
    __shared__ float sb[HID];
    __shared__ float sx[16][DIN];
    int n0 = blockIdx.x * 16;

    for (int i = tid; i < DIN * HID; i += 256) ((float*)sw)[i] = hw1[i];
    if (tid < HID) sb[tid] = hb1[tid];
    for (int i = tid; i < 16 * DIN; i += 256) {
        int r = i >> 6, d = i & 63;
        int n = n0 + r;
        float v = (d < 32) ? obs[(n & 511) * 32 + d] : lat[n * 32 + (d - 32)];
        sx[r][d] = v;
        g_x[n * DIN + d] = v;
    }
    __syncthreads();

    int r = tid >> 4, cg = tid & 15;
    float acc[8];
#pragma unroll
    for (int c = 0; c < 8; c++) acc[c] = 0.f;
#pragma unroll 8
    for (int d = 0; d < DIN; d++) {
        float a = sx[r][d];
        float4 w0 = *(const float4*)&sw[d][cg * 8];
        float4 w1 = *(const float4*)&sw[d][cg * 8 + 4];
        acc[0] += a * w0.x; acc[1] += a * w0.y;
        acc[2] += a * w0.z; acc[3] += a * w0.w;
        acc[4] += a * w1.x; acc[5] += a * w1.y;
        acc[6] += a * w1.z; acc[7] += a * w1.w;
    }
    int n = n0 + r;
    uint32_t hv[4];
#pragma unroll
    for (int j = 0; j < 4; j++)
        hv[j] = pack_h2(fmaxf(acc[2 * j] + sb[cg * 8 + 2 * j], 0.f),
                        fmaxf(acc[2 * j + 1] + sb[cg * 8 + 2 * j + 1], 0.f));
    uint8_t* base = (uint8_t*)g_abf + (n >> 7) * 34816 + (n & 127) * 272;
    *(uint4*)(base + cg * 16) = make_uint4(hv[0], hv[1], hv[2], hv[3]);
}

// ---------------------------------------------------------------------------
// Kernel 1: HMMA hypernet, 1-pass fp16, fat warp tiles.
// 512 CTAs x 128 thr (2 CTAs/SM). CTA = 64-row block x 16-d quarter.
// 4 warps = 2m x 2n, warp tile m32 x n64.
// smem: sA 17408 | SX 4352 | bias 1024 | B dbl 2x34816 = 92416
// ---------------------------------------------------------------------------
#define SA_OFF    0
#define SX_OFF    17408
#define SBIAS_OFF 21760
#define SB_OFF    22784
#define SB_TILE   34816
#define HSMEM     92416

__global__ __launch_bounds__(128, 2) void k_hyper_mma(const float* __restrict__ hb2) {
    extern __shared__ __align__(128) uint8_t smem[];
    const uint32_t sbase = smem_u32(smem);
    int tid = threadIdx.x, wid = tid >> 5, lane = tid & 31;
    int rb = blockIdx.x >> 2, dq = blockIdx.x & 3;   // rb 0..127 (64-row), dq 0..3
    int n0 = rb * 64, d0 = dq * 16;
    int wm = wid & 1, wn = wid >> 1;                 // 2m x 2n; warp tile 32x64

    {
        const uint4* asrc = &g_abf[(rb >> 1) * 2176 + (rb & 1) * 1088];
        for (int j = tid; j < 1088; j += 128) cp16(sbase + SA_OFF + j * 16, asrc + j);
        const uint4* bsrc = &g_bbf[d0 * 2176];
        for (int j = tid; j < 2176; j += 128) cp16(sbase + SB_OFF + j * 16, bsrc + j);
        if (tid < 32) cp16(sbase + SBIAS_OFF + tid * 16, (const uint4*)(hb2 + d0 * 128) + tid);
        CP_COMMIT();
    }
    float* SX = (float*)(smem + SX_OFF);   // [64][17]
    for (int i = tid; i < 64 * 16; i += 128) {
        int r = i >> 4, d = i & 15;
        SX[r * 17 + d] = g_x[(n0 + r) * 64 + d0 + d];
    }

    const int a_r = (lane & 15);
    const int a_kadd = (lane >> 4) * 8;
    const int bm = lane >> 3;
    const int b_n = ((bm >> 1) << 3) + (lane & 7);
    const int b_kadd = (bm & 1) * 8;
    const int r_q = lane >> 2;
    const int c_q = (lane & 3) * 2;

    float emb[2][8][4];
#pragma unroll
    for (int mt = 0; mt < 2; mt++)
#pragma unroll
        for (int t = 0; t < 8; t++)
#pragma unroll
            for (int c = 0; c < 4; c++) emb[mt][t][c] = 0.f;

    for (int i = 0; i < 16; i++) {
        int b = i & 1;
        if (i < 15) {
            const uint4* src = &g_bbf[(d0 + i + 1) * 2176];
            uint32_t dst = sbase + SB_OFF + (1 - b) * SB_TILE;
            for (int j = tid; j < 2176; j += 128) cp16(dst + j * 16, src + j);
            if (tid < 32)
                cp16(sbase + SBIAS_OFF + (1 - b) * 512 + tid * 16,
                     (const uint4*)(hb2 + (d0 + i + 1) * 128) + tid);
            CP_COMMIT();
            CP_WAIT(1);
        } else {
            CP_WAIT(0);
        }
        __syncthreads();

        const uint32_t Ab = sbase + SA_OFF;
        const uint32_t Bb = sbase + SB_OFF + b * SB_TILE;
        float S[2][8][4];
#pragma unroll
        for (int mt = 0; mt < 2; mt++)
#pragma unroll
            for (int t = 0; t < 8; t++)
#pragma unroll
                for (int c = 0; c < 4; c++) S[mt][t][c] = 0.f;

#pragma unroll
        for (int ks = 0; ks < 8; ks++) {
            uint32_t ah[2][4], bh[4][4];
            int ka = ks * 16 + a_kadd;
#pragma unroll
            for (int mt = 0; mt < 2; mt++) {
                int ar = wm * 32 + mt * 16 + a_r;
                ldsm_x4(ah[mt], Ab + ar * 272 + ka * 2);
            }
            int kb = ks * 16 + b_kadd;
#pragma unroll
            for (int nt = 0; nt < 4; nt++) {
                int nr = wn * 64 + nt * 16 + b_n;
                ldsm_x4(bh[nt], Bb + nr * 272 + kb * 2);
            }
#pragma unroll
            for (int mt = 0; mt < 2; mt++)
#pragma unroll
                for (int nt = 0; nt < 4; nt++) {
                    mma16816h(S[mt][nt * 2], ah[mt], bh[nt][0], bh[nt][1]);
                    mma16816h(S[mt][nt * 2 + 1], ah[mt], bh[nt][2], bh[nt][3]);
                }
        }
        const float* bias = (const float*)(smem + SBIAS_OFF) + b * 128;
#pragma unroll
        for (int mt = 0; mt < 2; mt++) {
            int rbase = wm * 32 + mt * 16 + r_q;
            float xlo = SX[rbase * 17 + i];
            float xhi = SX[(rbase + 8) * 17 + i];
#pragma unroll
            for (int t = 0; t < 8; t++) {
                int col = wn * 64 + t * 8 + c_q;
                float2 bv = *(const float2*)&bias[col];
                float* e = emb[mt][t];
                e[0] += xlo * fmaxf(S[mt][t][0] + bv.x, 0.f);
                e[1] += xlo * fmaxf(S[mt][t][1] + bv.y, 0.f);
                e[2] += xhi * fmaxf(S[mt][t][2] + bv.x, 0.f);
                e[3] += xhi * fmaxf(S[mt][t][3] + bv.y, 0.f);
            }
        }
        __syncthreads();
    }

    float* dst = g_embp + dq * (NTOT * HID) + n0 * 128;
#pragma unroll
    for (int mt = 0; mt < 2; mt++) {
        int row = wm * 32 + mt * 16 + r_q;
#pragma unroll
        for (int t = 0; t < 8; t++) {
            int col = wn * 64 + t * 8 + c_q;
            *(float2*)&dst[row * 128 + col] = make_float2(emb[mt][t][0], emb[mt][t][1]);
            *(float2*)&dst[(row + 8) * 128 + col] = make_float2(emb[mt][t][2], emb[mt][t][3]);
        }
    }
}

// ---------------------------------------------------------------------------
// Kernel 2: combine 4 partials (tanh) -> fp16 hi/lo emb tiles + mean tiles.
// ---------------------------------------------------------------------------
__global__ __launch_bounds__(256) void k_combine_mean() {
    __shared__ float2 red[4][64];
    int b = blockIdx.x, tid = threadIdx.x;
    int c2 = tid & 63, rg = tid >> 6;
    uint8_t* ebase = (uint8_t*)g_ebf + (b >> 3) * 67584 + ((b & 7) * 16) * 528;
    float2 sum = make_float2(0.f, 0.f);
#pragma unroll
    for (int r = 0; r < 4; r++) {
        int row = rg * 4 + r;
        int n = b * 16 + row;
        float a0 = 0.f, a1 = 0.f;
#pragma unroll
        for (int s = 0; s < 4; s++) {
            float2 p = *(const float2*)&g_embp[s * (NTOT * HID) + n * 128 + 2 * c2];
            a0 += p.x;
            a1 += p.y;
        }
        float v0 = tanhf(a0), v1 = tanhf(a1);
        sum.x += v0;
        sum.y += v1;
        uint32_t hi, lo;
        pack_hl2(v0, v1, hi, lo);
        *(uint32_t*)(ebase + row * 528 + c2 * 4) = hi;
        *(uint32_t*)(ebase + row * 528 + 256 + c2 * 4) = lo;
    }
    red[rg][c2] = sum;
    __syncthreads();
    if (rg == 0) {
        float2 m;
        m.x = (red[0][c2].x + red[1][c2].x + red[2][c2].x + red[3][c2].x) * (1.f / 16.f);
        m.y = (red[0][c2].y + red[1][c2].y + red[2][c2].y + red[3][c2].y) * (1.f / 16.f);
        uint32_t hi, lo;
        pack_hl2(m.x, m.y, hi, lo);
        uint8_t* mbase = (uint8_t*)g_mbf + (b >> 7) * 67584 + (b & 127) * 528;
        *(uint32_t*)(mbase + c2 * 4) = hi;
        *(uint32_t*)(mbase + 256 + c2 * 4) = lo;
    }
}

// ---------------------------------------------------------------------------
// Kernel 3: pipelined HMMA tail (3-pass, unchanged).
// ---------------------------------------------------------------------------
#define TA_OFF  0
#define TW0_OFF 67584
#define TW1_OFF 135168
#define TB_OFF  202752
#define T3_OFF  203776
#define TSMEM   204288

__device__ __forceinline__ void t_layer(uint32_t sbase, uint32_t Wb, int wm, int wn, int lane,
                                        float S[2][4][4]) {
    const int a_r = lane & 15, a_kadd = (lane >> 4) * 8;
    const int b_krow = lane & 15, b_nadd = (lane >> 4) * 8;
    const uint32_t Ab = sbase + TA_OFF;
#pragma unroll
    for (int ks = 0; ks < 8; ks++) {
        uint32_t ah[2][4], al[2][4], wh[2][4], wl[2][4];
        int ka = ks * 16 + a_kadd;
#pragma unroll
        for (int mt = 0; mt < 2; mt++) {
            int ar = wm * 32 + mt * 16 + a_r;
            ldsm_x4(ah[mt], Ab + ar * 528 + ka * 2);
            ldsm_x4(al[mt], Ab + ar * 528 + 256 + ka * 2);
        }
#pragma unroll
        for (int nt = 0; nt < 2; nt++) {
            uint32_t base = Wb + (ks * 16 + b_krow) * 528 + (wn * 32 + nt * 16 + b_nadd) * 2;
            ldsm_x4_t(wh[nt], base);
            ldsm_x4_t(wl[nt], base + 256);
        }
#pragma unroll
        for (int mt = 0; mt < 2; mt++)
#pragma unroll
            for (int nt = 0; nt < 2; nt++) {
                mma16816h(S[mt][nt * 2], ah[mt], wh[nt][0], wh[nt][1]);
                mma16816h(S[mt][nt * 2], al[mt], wh[nt][0], wh[nt][1]);
                mma16816h(S[mt][nt * 2], ah[mt], wl[nt][0], wl[nt][1]);
                mma16816h(S[mt][nt * 2 + 1], ah[mt], wh[nt][2], wh[nt][3]);
                mma16816h(S[mt][nt * 2 + 1], al[mt], wh[nt][2], wh[nt][3]);
                mma16816h(S[mt][nt * 2 + 1], ah[mt], wl[nt][2], wl[nt][3]);
            }
    }
}
__device__ __forceinline__ void t_act_to_sA(uint8_t* smem, const float* bias,
                                            int wm, int wn, int lane, float S[2][4][4]) {
    int r_q = lane >> 2, c_q = (lane & 3) * 2;
#pragma unroll
    for (int mt = 0; mt < 2; mt++) {
        int row = wm * 32 + mt * 16 + r_q;
#pragma unroll
        for (int t = 0; t < 4; t++) {
            int col = wn * 32 + t * 8 + c_q;
            float2 bv = *(const float2*)&bias[col];
            uint32_t hi, lo;
            pack_hl2(fmaxf(S[mt][t][0] + bv.x, 0.f), fmaxf(S[mt][t][1] + bv.y, 0.f), hi, lo);
            *(uint32_t*)(smem + TA_OFF + row * 528 + col * 2) = hi;
            *(uint32_t*)(smem + TA_OFF + row * 528 + 256 + col * 2) = lo;
            pack_hl2(fmaxf(S[mt][t][2] + bv.x, 0.f), fmaxf(S[mt][t][3] + bv.y, 0.f), hi, lo);
            *(uint32_t*)(smem + TA_OFF + (row + 8) * 528 + col * 2) = hi;
            *(uint32_t*)(smem + TA_OFF + (row + 8) * 528 + 256 + col * 2) = lo;
        }
    }
}

__global__ __launch_bounds__(512, 1) void k_tail_mma(
    const float* __restrict__ vb1, const float* __restrict__ vb2,
    const float* __restrict__ ab1, const float* __restrict__ ab2,
    const float* __restrict__ aw3, const float* __restrict__ ab3) {
    extern __shared__ __align__(128) uint8_t smem[];
    const uint32_t sbase = smem_u32(smem);
    int tid = threadIdx.x, wid = tid >> 5, lane = tid & 31;
    int wm = wid & 3, wn = wid >> 2;
    int r_q = lane >> 2, c_q = (lane & 3) * 2;
    float* b0 = (float*)(smem + TB_OFF);
    float* b1 = b0 + 128;

    float S[2][4][4];
#define ZERO_S() { _Pragma("unroll") for (int mt = 0; mt < 2; mt++) \
    _Pragma("unroll") for (int t = 0; t < 4; t++) \
    _Pragma("unroll") for (int c = 0; c < 4; c++) S[mt][t][c] = 0.f; }

    if (blockIdx.x < 64) {
        int n0 = blockIdx.x * 128;
        for (int j = tid; j < 4224; j += 512) cp16(sbase + TA_OFF + j * 16, &g_ebf[blockIdx.x * 4224 + j]);
        for (int j = tid; j < 4224; j += 512) cp16(sbase + TW0_OFF + j * 16, &g_wbf[0 * 4224 + j]);
        CP_COMMIT();
        for (int j = tid; j < 4224; j += 512) cp16(sbase + TW1_OFF + j * 16, &g_wbf[1 * 4224 + j]);
        CP_COMMIT();
        if (tid < 128) b0[tid] = vb1[tid];
        else if (tid < 256) b1[tid - 128] = vb2[tid - 128];
        CP_WAIT(1);
        __syncthreads();
        ZERO_S();
        t_layer(sbase, sbase + TW0_OFF, wm, wn, lane, S);
        __syncthreads();
        t_act_to_sA(smem, b0, wm, wn, lane, S);
        CP_WAIT(0);
        __syncthreads();
        ZERO_S();
        t_layer(sbase, sbase + TW1_OFF, wm, wn, lane, S);
#pragma unroll
        for (int mt = 0; mt < 2; mt++) {
            int row = wm * 32 + mt * 16 + r_q;
#pragma unroll
            for (int t = 0; t < 4; t++) {
                int col = wn * 32 + t * 8 + c_q;
                float2 bv = *(const float2*)&b1[col];
                *(float2*)&g_vals[(n0 + row) * 128 + col] =
                    make_float2(fmaxf(S[mt][t][0] + bv.x, 0.f), fmaxf(S[mt][t][1] + bv.y, 0.f));
                *(float2*)&g_vals[(n0 + row + 8) * 128 + col] =
                    make_float2(fmaxf(S[mt][t][2] + bv.x, 0.f), fmaxf(S[mt][t][3] + bv.y, 0.f));
            }
        }
    } else {
        int cb = blockIdx.x - 64;
        int n0 = cb * 128;
        for (int j = tid; j < 4224; j += 512) cp16(sbase + TA_OFF + j * 16, &g_ebf[cb * 4224 + j]);
        for (int j = tid; j < 4224; j += 512) cp16(sbase + TW0_OFF + j * 16, &g_wbf[2 * 4224 + j]);
        CP_COMMIT();
        for (int j = tid; j < 4224; j += 512) cp16(sbase + TW1_OFF + j * 16, &g_wbf[3 * 4224 + j]);
        CP_COMMIT();
        if (tid < 128) b0[tid] = ab1[tid];
        else if (tid < 256) b1[tid - 128] = ab2[tid - 128];
        else if (tid < 384) ((float*)(smem + T3_OFF))[tid - 256] = aw3[tid - 256];
        CP_WAIT(1);
        __syncthreads();
        ZERO_S();
        t_layer(sbase, sbase + TW0_OFF, wm, wn, lane, S);  // layer1a
        __syncthreads();
        for (int j = tid; j < 4224; j += 512) cp16(sbase + TA_OFF + j * 16, &g_mbf[(cb & 3) * 4224 + j]);
        CP_COMMIT();
        for (int j = tid; j < 4224; j += 512) cp16(sbase + TW0_OFF + j * 16, &g_wbf[4 * 4224 + j]);
        CP_COMMIT();
        CP_WAIT(1);
        __syncthreads();
        t_layer(sbase, sbase + TW1_OFF, wm, wn, lane, S);  // layer1b
        __syncthreads();
        t_act_to_sA(smem, b0, wm, wn, lane, S);
        CP_WAIT(0);
        __syncthreads();
        ZERO_S();
        t_layer(sbase, sbase + TW0_OFF, wm, wn, lane, S);  // layer2
        __syncthreads();
        t_act_to_sA(smem, b1, wm, wn, lane, S);
        __syncthreads();
        const float* sw3 = (const float*)(smem + T3_OFF);
        int row = tid >> 2, l4 = tid & 3;
        float s = 0.f;
#pragma unroll
        for (int j = 0; j < 32; j++) {
            int k = l4 * 32 + j;
            float hi = __half2float(*(const __half*)(smem + TA_OFF + row * 528 + k * 2));
            float lo = __half2float(*(const __half*)(smem + TA_OFF + row * 528 + 256 + k * 2));
            s += (hi + lo) * sw3[k];
        }
        s += __shfl_xor_sync(0xffffffffu, s, 1);
        s += __shfl_xor_sync(0xffffffffu, s, 2);
        if (l4 == 0) g_sc[n0 + row] = s + ab3[0];
    }
}

// ---------------------------------------------------------------------------
// Kernel 4: softmax over 16 + weighted sum -> out[512,128]
// ---------------------------------------------------------------------------
__global__ void k_final(float* __restrict__ out) {
    __shared__ float sc[NADV];
    int b = blockIdx.x, tid = threadIdx.x;
    if (tid < NADV) sc[tid] = g_sc[b * NADV + tid];
    __syncthreads();
    float m = sc[0];
#pragma unroll
    for (int a = 1; a < NADV; a++) m = fmaxf(m, sc[a]);
    float den = 0.f, o = 0.f;
#pragma unroll
    for (int a = 0; a < NADV; a++) {
        float e = expf(sc[a] - m);
        den += e;
        o += e * g_vals[(b * NADV + a) * HID + tid];
    }
    out[b * HID + tid] = o / den;
}

// ---------------------------------------------------------------------------
extern "C" void kernel_launch(void* const* d_in, const int* in_sizes, int n_in,
                              void* d_out, int out_size) {
    const float* obs = (const float*)d_in[0];
    const float* lat = (const float*)d_in[1];
    const float* hw1 = (const float*)d_in[2];
    const float* hb1 = (const float*)d_in[3];
    const float* hw2 = (const float*)d_in[4];
    const float* hb2 = (const float*)d_in[5];
    const float* vw1 = (const float*)d_in[6];
    const float* vb1 = (const float*)d_in[7];
    const float* vw2 = (const float*)d_in[8];
    const float* vb2 = (const float*)d_in[9];
    const float* aw1 = (const float*)d_in[10];
    const float* ab1 = (const float*)d_in[11];
    const float* aw2 = (const float*)d_in[12];
    const float* ab2 = (const float*)d_in[13];
    const float* aw3 = (const float*)d_in[14];
    const float* ab3 = (const float*)d_in[15];
    float* out = (float*)d_out;

    static int attr_set = 0;
    if (!attr_set) {
        cudaFuncSetAttribute(k_hyper_mma, cudaFuncAttributeMaxDynamicSharedMemorySize, HSMEM);
        cudaFuncSetAttribute(k_tail_mma, cudaFuncAttributeMaxDynamicSharedMemorySize, TSMEM);
        attr_set = 1;
    }

    k_prep<<<1064, 256>>>(obs, lat, hw1, hb1, hw2, vw1, vw2, aw1, aw2);  // 0
    k_hyper_mma<<<512, 128, HSMEM>>>(hb2);                               // 1
    k_combine_mean<<<BATCH, 256>>>();                                    // 2
    k_tail_mma<<<128, 512, TSMEM>>>(vb1, vb2, ab1, ab2, aw3, ab3);       // 3
    k_final<<<BATCH, HID>>>(out);                                        // 4
}

// round 13
// speedup vs baseline: 1.0324x; 1.0324x over previous
#include <cuda_runtime.h>
#include <cuda_fp16.h>
#include <math.h>
#include <stdint.h>

// Problem constants
#define NTOT 8192   // B * A
#define BATCH 512
#define NADV 16
#define DIN 64      // DS + DO
#define HID 128

// Scratch
__device__ float g_x[NTOT * DIN];
__device__ float g_embp[4 * NTOT * HID];   // partial einsum sums (pre-tanh), 4 d-quarters
__device__ float g_vals[NTOT * HID];
__device__ float g_sc[NTOT];
// Hyper A tiles: fp16 hi only, pitch 272B; 128-row tile = 34816B = 2176 uint4
__device__ uint4 g_abf[64 * 2176];
// Tail tiles: fp16 hi/lo, pitch 528B; 128-row tile = 67584B = 4224 uint4
__device__ uint4 g_ebf[64 * 4224];   // emb tiles (tail A)
__device__ uint4 g_mbf[4 * 4224];    // mean tiles
__device__ uint4 g_wbf[5 * 4224];    // tail weights: vw1,vw2,aw1a,aw1b,aw2 ([k][n])
// Hyper B tiles: fp16 hi only, pitch 272B; tile = 34816B = 2176 uint4
__device__ uint4 g_bbf[64 * 2176];

// ---------------------------------------------------------------------------
// helpers
// ---------------------------------------------------------------------------
__device__ __forceinline__ uint32_t smem_u32(const void* p) {
    uint32_t a;
    asm("{ .reg .u64 t; cvta.to.shared.u64 t, %1; cvt.u32.u64 %0, t; }" : "=r"(a) : "l"(p));
    return a;
}
__device__ __forceinline__ void f2hl16(float v, uint16_t& h, uint16_t& l) {
    __half hh = __float2half_rn(v);
    float r = v - __half2float(hh);
    __half hl = __float2half_rn(r);
    h = __half_as_ushort(hh);
    l = __half_as_ushort(hl);
}
__device__ __forceinline__ void pack_hl2(float v0, float v1, uint32_t& hi, uint32_t& lo) {
    uint16_t h0, l0, h1, l1;
    f2hl16(v0, h0, l0);
    f2hl16(v1, h1, l1);
    hi = (uint32_t)h0 | ((uint32_t)h1 << 16);
    lo = (uint32_t)l0 | ((uint32_t)l1 << 16);
}
__device__ __forceinline__ uint32_t pack_h2(float v0, float v1) {
    return (uint32_t)__half_as_ushort(__float2half_rn(v0)) |
           ((uint32_t)__half_as_ushort(__float2half_rn(v1)) << 16);
}
__device__ __forceinline__ void ldsm_x4(uint32_t* r, uint32_t addr) {
    asm volatile("ldmatrix.sync.aligned.m8n8.x4.shared.b16 {%0,%1,%2,%3}, [%4];"
                 : "=r"(r[0]), "=r"(r[1]), "=r"(r[2]), "=r"(r[3]) : "r"(addr));
}
__device__ __forceinline__ void ldsm_x4_t(uint32_t* r, uint32_t addr) {
    asm volatile("ldmatrix.sync.aligned.m8n8.x4.trans.shared.b16 {%0,%1,%2,%3}, [%4];"
                 : "=r"(r[0]), "=r"(r[1]), "=r"(r[2]), "=r"(r[3]) : "r"(addr));
}
__device__ __forceinline__ void mma16816h(float* d, const uint32_t* a, uint32_t b0, uint32_t b1) {
    asm volatile(
        "mma.sync.aligned.m16n8k16.row.col.f32.f16.f16.f32 "
        "{%0,%1,%2,%3}, {%4,%5,%6,%7}, {%8,%9}, {%0,%1,%2,%3};"
        : "+f"(d[0]), "+f"(d[1]), "+f"(d[2]), "+f"(d[3])
        : "r"(a[0]), "r"(a[1]), "r"(a[2]), "r"(a[3]), "r"(b0), "r"(b1));
}
__device__ __forceinline__ void cp16(uint32_t dst, const void* src) {
    asm volatile("cp.async.cg.shared.global [%0], [%1], 16;" :: "r"(dst), "l"(src) : "memory");
}
#define CP_COMMIT() asm volatile("cp.async.commit_group;" ::: "memory")
#define CP_WAIT(N)  asm volatile("cp.async.wait_group %0;" :: "n"(N) : "memory")

// ---------------------------------------------------------------------------
// Kernel 0 (fused prep): blocks 0..511 h1 -> A tiles + g_x;
//   512..1023: hw2 -> B tiles;  1024..1063: tail weights -> g_wbf
// ---------------------------------------------------------------------------
__global__ __launch_bounds__(256) void k_prep(
    const float* __restrict__ obs, const float* __restrict__ lat,
    const float* __restrict__ hw1, const float* __restrict__ hb1,
    const float* __restrict__ hw2,
    const float* __restrict__ vw1, const float* __restrict__ vw2,
    const float* __restrict__ aw1, const float* __restrict__ aw2) {
    int tid = threadIdx.x;
    if (blockIdx.x >= 1024) {
        int idx = (blockIdx.x - 1024) * 256 + tid;  // 10240
        int t = idx >> 11, rem = idx & 2047;
        int k = rem >> 4, c = rem & 15;
        const float* W = (t == 0) ? vw1 : (t == 1) ? vw2 : (t == 2) ? aw1
                         : (t == 3) ? (aw1 + 16384) : aw2;
        uint32_t hi[4], lo[4];
#pragma unroll
        for (int j = 0; j < 4; j++) {
            float2 v = *(const float2*)(W + k * 128 + c * 8 + 2 * j);
            pack_hl2(v.x, v.y, hi[j], lo[j]);
        }
        uint8_t* base = (uint8_t*)g_wbf + t * 67584 + k * 528;
        *(uint4*)(base + c * 16) = make_uint4(hi[0], hi[1], hi[2], hi[3]);
        *(uint4*)(base + 256 + c * 16) = make_uint4(lo[0], lo[1], lo[2], lo[3]);
        return;
    }
    if (blockIdx.x >= 512) {
        int idx = (blockIdx.x - 512) * 256 + tid;   // 131072
        int n = idx & 127, kc = (idx >> 7) & 15, d = idx >> 11;
        int k0 = kc * 8;
        uint32_t hv[4];
#pragma unroll
        for (int j = 0; j < 4; j++) {
            float v0 = hw2[(k0 + 2 * j) * 8192 + d * 128 + n];
            float v1 = hw2[(k0 + 2 * j + 1) * 8192 + d * 128 + n];
            hv[j] = pack_h2(v0, v1);
        }
        uint8_t* base = (uint8_t*)g_bbf + d * 34816 + n * 272;
        *(uint4*)(base + k0 * 2) = make_uint4(hv[0], hv[1], hv[2], hv[3]);
        return;
    }
    // ---- build h1 ----
    __shared__ __align__(16) float sw[DIN][HID];
    __shared__ float sb[HID];
    __shared__ float sx[16][DIN];
    int n0 = blockIdx.x * 16;

    for (int i = tid; i < DIN * HID; i += 256) ((float*)sw)[i] = hw1[i];
    if (tid < HID) sb[tid] = hb1[tid];
    for (int i = tid; i < 16 * DIN; i += 256) {
        int r = i >> 6, d = i & 63;
        int n = n0 + r;
        float v = (d < 32) ? obs[(n & 511) * 32 + d] : lat[n * 32 + (d - 32)];
        sx[r][d] = v;
        g_x[n * DIN + d] = v;
    }
    __syncthreads();

    int r = tid >> 4, cg = tid & 15;
    float acc[8];
#pragma unroll
    for (int c = 0; c < 8; c++) acc[c] = 0.f;
#pragma unroll 8
    for (int d = 0; d < DIN; d++) {
        float a = sx[r][d];
        float4 w0 = *(const float4*)&sw[d][cg * 8];
        float4 w1 = *(const float4*)&sw[d][cg * 8 + 4];
        acc[0] += a * w0.x; acc[1] += a * w0.y;
        acc[2] += a * w0.z; acc[3] += a * w0.w;
        acc[4] += a * w1.x; acc[5] += a * w1.y;
        acc[6] += a * w1.z; acc[7] += a * w1.w;
    }
    int n = n0 + r;
    uint32_t hv[4];
#pragma unroll
    for (int j = 0; j < 4; j++)
        hv[j] = pack_h2(fmaxf(acc[2 * j] + sb[cg * 8 + 2 * j], 0.f),
                        fmaxf(acc[2 * j + 1] + sb[cg * 8 + 2 * j + 1], 0.f));
    uint8_t* base = (uint8_t*)g_abf + (n >> 7) * 34816 + (n & 127) * 272;
    *(uint4*)(base + cg * 16) = make_uint4(hv[0], hv[1], hv[2], hv[3]);
}

// ---------------------------------------------------------------------------
// Kernel 1: HMMA hypernet, 1-pass fp16, R11 warp config + finer d-split.
// 512 CTAs x 256 thr (2 CTAs/SM). CTA = 64-row block x 16-d quarter.
// 8 warps = 2m x 4n, warp tile m32 x n32.
// smem: sA 17408 | SX 4352 | bias 1024 | B dbl 2x34816 = 92416
// ---------------------------------------------------------------------------
#define SA_OFF    0
#define SX_OFF    17408
#define SBIAS_OFF 21760
#define SB_OFF    22784
#define SB_TILE   34816
#define HSMEM     92416

__global__ __launch_bounds__(256, 2) void k_hyper_mma(const float* __restrict__ hb2) {
    extern __shared__ __align__(128) uint8_t smem[];
    const uint32_t sbase = smem_u32(smem);
    int tid = threadIdx.x, wid = tid >> 5, lane = tid & 31;
    int rb = blockIdx.x >> 2, dq = blockIdx.x & 3;   // rb 0..127 (64-row), dq 0..3
    int n0 = rb * 64, d0 = dq * 16;
    int wm = wid & 1, wn = wid >> 1;                 // 2m x 4n; warp tile 32x32

    {
        const uint4* asrc = &g_abf[(rb >> 1) * 2176 + (rb & 1) * 1088];
        for (int j = tid; j < 1088; j += 256) cp16(sbase + SA_OFF + j * 16, asrc + j);
        const uint4* bsrc = &g_bbf[d0 * 2176];
        for (int j = tid; j < 2176; j += 256) cp16(sbase + SB_OFF + j * 16, bsrc + j);
        if (tid < 32) cp16(sbase + SBIAS_OFF + tid * 16, (const uint4*)(hb2 + d0 * 128) + tid);
        CP_COMMIT();
    }
    float* SX = (float*)(smem + SX_OFF);   // [64][17]
    for (int i = tid; i < 64 * 16; i += 256) {
        int r = i >> 4, d = i & 15;
        SX[r * 17 + d] = g_x[(n0 + r) * 64 + d0 + d];
    }

    const int a_r = (lane & 15);
    const int a_kadd = (lane >> 4) * 8;
    const int bm = lane >> 3;
    const int b_n = ((bm >> 1) << 3) + (lane & 7);
    const int b_kadd = (bm & 1) * 8;
    const int r_q = lane >> 2;
    const int c_q = (lane & 3) * 2;

    float emb[2][4][4];
#pragma unroll
    for (int mt = 0; mt < 2; mt++)
#pragma unroll
        for (int t = 0; t < 4; t++)
#pragma unroll
            for (int c = 0; c < 4; c++) emb[mt][t][c] = 0.f;

    for (int i = 0; i < 16; i++) {
        int b = i & 1;
        if (i < 15) {
            const uint4* src = &g_bbf[(d0 + i + 1) * 2176];
            uint32_t dst = sbase + SB_OFF + (1 - b) * SB_TILE;
            for (int j = tid; j < 2176; j += 256) cp16(dst + j * 16, src + j);
            if (tid < 32)
                cp16(sbase + SBIAS_OFF + (1 - b) * 512 + tid * 16,
                     (const uint4*)(hb2 + (d0 + i + 1) * 128) + tid);
            CP_COMMIT();
            CP_WAIT(1);
        } else {
            CP_WAIT(0);
        }
        __syncthreads();

        const uint32_t Ab = sbase + SA_OFF;
        const uint32_t Bb = sbase + SB_OFF + b * SB_TILE;
        float S[2][4][4];
#pragma unroll
        for (int mt = 0; mt < 2; mt++)
#pragma unroll
            for (int t = 0; t < 4; t++)
#pragma unroll
                for (int c = 0; c < 4; c++) S[mt][t][c] = 0.f;

#pragma unroll
        for (int ks = 0; ks < 8; ks++) {
            uint32_t ah[2][4], bh[2][4];
            int ka = ks * 16 + a_kadd;
#pragma unroll
            for (int mt = 0; mt < 2; mt++) {
                int ar = wm * 32 + mt * 16 + a_r;
                ldsm_x4(ah[mt], Ab + ar * 272 + ka * 2);
            }
            int kb = ks * 16 + b_kadd;
#pragma unroll
            for (int nt = 0; nt < 2; nt++) {
                int nr = wn * 32 + nt * 16 + b_n;
                ldsm_x4(bh[nt], Bb + nr * 272 + kb * 2);
            }
#pragma unroll
            for (int mt = 0; mt < 2; mt++)
#pragma unroll
                for (int nt = 0; nt < 2; nt++) {
                    mma16816h(S[mt][nt * 2], ah[mt], bh[nt][0], bh[nt][1]);
                    mma16816h(S[mt][nt * 2 + 1], ah[mt], bh[nt][2], bh[nt][3]);
                }
        }
        const float* bias = (const float*)(smem + SBIAS_OFF) + b * 128;
#pragma unroll
        for (int mt = 0; mt < 2; mt++) {
            int rbase = wm * 32 + mt * 16 + r_q;
            float xlo = SX[rbase * 17 + i];
            float xhi = SX[(rbase + 8) * 17 + i];
#pragma unroll
            for (int t = 0; t < 4; t++) {
                int col = wn * 32 + t * 8 + c_q;
                float2 bv = *(const float2*)&bias[col];
                float* e = emb[mt][t];
                e[0] += xlo * fmaxf(S[mt][t][0] + bv.x, 0.f);
                e[1] += xlo * fmaxf(S[mt][t][1] + bv.y, 0.f);
                e[2] += xhi * fmaxf(S[mt][t][2] + bv.x, 0.f);
                e[3] += xhi * fmaxf(S[mt][t][3] + bv.y, 0.f);
            }
        }
        __syncthreads();
    }

    float* dst = g_embp + dq * (NTOT * HID) + n0 * 128;
#pragma unroll
    for (int mt = 0; mt < 2; mt++) {
        int row = wm * 32 + mt * 16 + r_q;
#pragma unroll
        for (int t = 0; t < 4; t++) {
            int col = wn * 32 + t * 8 + c_q;
            *(float2*)&dst[row * 128 + col] = make_float2(emb[mt][t][0], emb[mt][t][1]);
            *(float2*)&dst[(row + 8) * 128 + col] = make_float2(emb[mt][t][2], emb[mt][t][3]);
        }
    }
}

// ---------------------------------------------------------------------------
// Kernel 2: combine 4 partials (tanh) -> fp16 hi/lo emb tiles + mean tiles.
// ---------------------------------------------------------------------------
__global__ __launch_bounds__(256) void k_combine_mean() {
    __shared__ float2 red[4][64];
    int b = blockIdx.x, tid = threadIdx.x;
    int c2 = tid & 63, rg = tid >> 6;
    uint8_t* ebase = (uint8_t*)g_ebf + (b >> 3) * 67584 + ((b & 7) * 16) * 528;
    float2 sum = make_float2(0.f, 0.f);
#pragma unroll
    for (int r = 0; r < 4; r++) {
        int row = rg * 4 + r;
        int n = b * 16 + row;
        float a0 = 0.f, a1 = 0.f;
#pragma unroll
        for (int s = 0; s < 4; s++) {
            float2 p = *(const float2*)&g_embp[s * (NTOT * HID) + n * 128 + 2 * c2];
            a0 += p.x;
            a1 += p.y;
        }
        float v0 = tanhf(a0), v1 = tanhf(a1);
        sum.x += v0;
        sum.y += v1;
        uint32_t hi, lo;
        pack_hl2(v0, v1, hi, lo);
        *(uint32_t*)(ebase + row * 528 + c2 * 4) = hi;
        *(uint32_t*)(ebase + row * 528 + 256 + c2 * 4) = lo;
    }
    red[rg][c2] = sum;
    __syncthreads();
    if (rg == 0) {
        float2 m;
        m.x = (red[0][c2].x + red[1][c2].x + red[2][c2].x + red[3][c2].x) * (1.f / 16.f);
        m.y = (red[0][c2].y + red[1][c2].y + red[2][c2].y + red[3][c2].y) * (1.f / 16.f);
        uint32_t hi, lo;
        pack_hl2(m.x, m.y, hi, lo);
        uint8_t* mbase = (uint8_t*)g_mbf + (b >> 7) * 67584 + (b & 127) * 528;
        *(uint32_t*)(mbase + c2 * 4) = hi;
        *(uint32_t*)(mbase + 256 + c2 * 4) = lo;
    }
}

// ---------------------------------------------------------------------------
// Kernel 3: pipelined HMMA tail (3-pass, unchanged).
// ---------------------------------------------------------------------------
#define TA_OFF  0
#define TW0_OFF 67584
#define TW1_OFF 135168
#define TB_OFF  202752
#define T3_OFF  203776
#define TSMEM   204288

__device__ __forceinline__ void t_layer(uint32_t sbase, uint32_t Wb, int wm, int wn, int lane,
                                        float S[2][4][4]) {
    const int a_r = lane & 15, a_kadd = (lane >> 4) * 8;
    const int b_krow = lane & 15, b_nadd = (lane >> 4) * 8;
    const uint32_t Ab = sbase + TA_OFF;
#pragma unroll
    for (int ks = 0; ks < 8; ks++) {
        uint32_t ah[2][4], al[2][4], wh[2][4], wl[2][4];
        int ka = ks * 16 + a_kadd;
#pragma unroll
        for (int mt = 0; mt < 2; mt++) {
            int ar = wm * 32 + mt * 16 + a_r;
            ldsm_x4(ah[mt], Ab + ar * 528 + ka * 2);
            ldsm_x4(al[mt], Ab + ar * 528 + 256 + ka * 2);
        }
#pragma unroll
        for (int nt = 0; nt < 2; nt++) {
            uint32_t base = Wb + (ks * 16 + b_krow) * 528 + (wn * 32 + nt * 16 + b_nadd) * 2;
            ldsm_x4_t(wh[nt], base);
            ldsm_x4_t(wl[nt], base + 256);
        }
#pragma unroll
        for (int mt = 0; mt < 2; mt++)
#pragma unroll
            for (int nt = 0; nt < 2; nt++) {
                mma16816h(S[mt][nt * 2], ah[mt], wh[nt][0], wh[nt][1]);
                mma16816h(S[mt][nt * 2], al[mt], wh[nt][0], wh[nt][1]);
                mma16816h(S[mt][nt * 2], ah[mt], wl[nt][0], wl[nt][1]);
                mma16816h(S[mt][nt * 2 + 1], ah[mt], wh[nt][2], wh[nt][3]);
                mma16816h(S[mt][nt * 2 + 1], al[mt], wh[nt][2], wh[nt][3]);
                mma16816h(S[mt][nt * 2 + 1], ah[mt], wl[nt][2], wl[nt][3]);
            }
    }
}
__device__ __forceinline__ void t_act_to_sA(uint8_t* smem, const float* bias,
                                            int wm, int wn, int lane, float S[2][4][4]) {
    int r_q = lane >> 2, c_q = (lane & 3) * 2;
#pragma unroll
    for (int mt = 0; mt < 2; mt++) {
        int row = wm * 32 + mt * 16 + r_q;
#pragma unroll
        for (int t = 0; t < 4; t++) {
            int col = wn * 32 + t * 8 + c_q;
            float2 bv = *(const float2*)&bias[col];
            uint32_t hi, lo;
            pack_hl2(fmaxf(S[mt][t][0] + bv.x, 0.f), fmaxf(S[mt][t][1] + bv.y, 0.f), hi, lo);
            *(uint32_t*)(smem + TA_OFF + row * 528 + col * 2) = hi;
            *(uint32_t*)(smem + TA_OFF + row * 528 + 256 + col * 2) = lo;
            pack_hl2(fmaxf(S[mt][t][2] + bv.x, 0.f), fmaxf(S[mt][t][3] + bv.y, 0.f), hi, lo);
            *(uint32_t*)(smem + TA_OFF + (row + 8) * 528 + col * 2) = hi;
            *(uint32_t*)(smem + TA_OFF + (row + 8) * 528 + 256 + col * 2) = lo;
        }
    }
}

__global__ __launch_bounds__(512, 1) void k_tail_mma(
    const float* __restrict__ vb1, const float* __restrict__ vb2,
    const float* __restrict__ ab1, const float* __restrict__ ab2,
    const float* __restrict__ aw3, const float* __restrict__ ab3) {
    extern __shared__ __align__(128) uint8_t smem[];
    const uint32_t sbase = smem_u32(smem);
    int tid = threadIdx.x, wid = tid >> 5, lane = tid & 31;
    int wm = wid & 3, wn = wid >> 2;
    int r_q = lane >> 2, c_q = (lane & 3) * 2;
    float* b0 = (float*)(smem + TB_OFF);
    float* b1 = b0 + 128;

    float S[2][4][4];
#define ZERO_S() { _Pragma("unroll") for (int mt = 0; mt < 2; mt++) \
    _Pragma("unroll") for (int t = 0; t < 4; t++) \
    _Pragma("unroll") for (int c = 0; c < 4; c++) S[mt][t][c] = 0.f; }

    if (blockIdx.x < 64) {
        int n0 = blockIdx.x * 128;
        for (int j = tid; j < 4224; j += 512) cp16(sbase + TA_OFF + j * 16, &g_ebf[blockIdx.x * 4224 + j]);
        for (int j = tid; j < 4224; j += 512) cp16(sbase + TW0_OFF + j * 16, &g_wbf[0 * 4224 + j]);
        CP_COMMIT();
        for (int j = tid; j < 4224; j += 512) cp16(sbase + TW1_OFF + j * 16, &g_wbf[1 * 4224 + j]);
        CP_COMMIT();
        if (tid < 128) b0[tid] = vb1[tid];
        else if (tid < 256) b1[tid - 128] = vb2[tid - 128];
        CP_WAIT(1);
        __syncthreads();
        ZERO_S();
        t_layer(sbase, sbase + TW0_OFF, wm, wn, lane, S);
        __syncthreads();
        t_act_to_sA(smem, b0, wm, wn, lane, S);
        CP_WAIT(0);
        __syncthreads();
        ZERO_S();
        t_layer(sbase, sbase + TW1_OFF, wm, wn, lane, S);
#pragma unroll
        for (int mt = 0; mt < 2; mt++) {
            int row = wm * 32 + mt * 16 + r_q;
#pragma unroll
            for (int t = 0; t < 4; t++) {
                int col = wn * 32 + t * 8 + c_q;
                float2 bv = *(const float2*)&b1[col];
                *(float2*)&g_vals[(n0 + row) * 128 + col] =
                    make_float2(fmaxf(S[mt][t][0] + bv.x, 0.f), fmaxf(S[mt][t][1] + bv.y, 0.f));
                *(float2*)&g_vals[(n0 + row + 8) * 128 + col] =
                    make_float2(fmaxf(S[mt][t][2] + bv.x, 0.f), fmaxf(S[mt][t][3] + bv.y, 0.f));
            }
        }
    } else {
        int cb = blockIdx.x - 64;
        int n0 = cb * 128;
        for (int j = tid; j < 4224; j += 512) cp16(sbase + TA_OFF + j * 16, &g_ebf[cb * 4224 + j]);
        for (int j = tid; j < 4224; j += 512) cp16(sbase + TW0_OFF + j * 16, &g_wbf[2 * 4224 + j]);
        CP_COMMIT();
        for (int j = tid; j < 4224; j += 512) cp16(sbase + TW1_OFF + j * 16, &g_wbf[3 * 4224 + j]);
        CP_COMMIT();
        if (tid < 128) b0[tid] = ab1[tid];
        else if (tid < 256) b1[tid - 128] = ab2[tid - 128];
        else if (tid < 384) ((float*)(smem + T3_OFF))[tid - 256] = aw3[tid - 256];
        CP_WAIT(1);
        __syncthreads();
        ZERO_S();
        t_layer(sbase, sbase + TW0_OFF, wm, wn, lane, S);  // layer1a
        __syncthreads();
        for (int j = tid; j < 4224; j += 512) cp16(sbase + TA_OFF + j * 16, &g_mbf[(cb & 3) * 4224 + j]);
        CP_COMMIT();
        for (int j = tid; j < 4224; j += 512) cp16(sbase + TW0_OFF + j * 16, &g_wbf[4 * 4224 + j]);
        CP_COMMIT();
        CP_WAIT(1);
        __syncthreads();
        t_layer(sbase, sbase + TW1_OFF, wm, wn, lane, S);  // layer1b
        __syncthreads();
        t_act_to_sA(smem, b0, wm, wn, lane, S);
        CP_WAIT(0);
        __syncthreads();
        ZERO_S();
        t_layer(sbase, sbase + TW0_OFF, wm, wn, lane, S);  // layer2
        __syncthreads();
        t_act_to_sA(smem, b1, wm, wn, lane, S);
        __syncthreads();
        const float* sw3 = (const float*)(smem + T3_OFF);
        int row = tid >> 2, l4 = tid & 3;
        float s = 0.f;
#pragma unroll
        for (int j = 0; j < 32; j++) {
            int k = l4 * 32 + j;
            float hi = __half2float(*(const __half*)(smem + TA_OFF + row * 528 + k * 2));
            float lo = __half2float(*(const __half*)(smem + TA_OFF + row * 528 + 256 + k * 2));
            s += (hi + lo) * sw3[k];
        }
        s += __shfl_xor_sync(0xffffffffu, s, 1);
        s += __shfl_xor_sync(0xffffffffu, s, 2);
        if (l4 == 0) g_sc[n0 + row] = s + ab3[0];
    }
}

// ---------------------------------------------------------------------------
// Kernel 4: softmax over 16 + weighted sum -> out[512,128]
// ---------------------------------------------------------------------------
__global__ void k_final(float* __restrict__ out) {
    __shared__ float sc[NADV];
    int b = blockIdx.x, tid = threadIdx.x;
    if (tid < NADV) sc[tid] = g_sc[b * NADV + tid];
    __syncthreads();
    float m = sc[0];
#pragma unroll
    for (int a = 1; a < NADV; a++) m = fmaxf(m, sc[a]);
    float den = 0.f, o = 0.f;
#pragma unroll
    for (int a = 0; a < NADV; a++) {
        float e = expf(sc[a] - m);
        den += e;
        o += e * g_vals[(b * NADV + a) * HID + tid];
    }
    out[b * HID + tid] = o / den;
}

// ---------------------------------------------------------------------------
extern "C" void kernel_launch(void* const* d_in, const int* in_sizes, int n_in,
                              void* d_out, int out_size) {
    const float* obs = (const float*)d_in[0];
    const float* lat = (const float*)d_in[1];
    const float* hw1 = (const float*)d_in[2];
    const float* hb1 = (const float*)d_in[3];
    const float* hw2 = (const float*)d_in[4];
    const float* hb2 = (const float*)d_in[5];
    const float* vw1 = (const float*)d_in[6];
    const float* vb1 = (const float*)d_in[7];
    const float* vw2 = (const float*)d_in[8];
    const float* vb2 = (const float*)d_in[9];
    const float* aw1 = (const float*)d_in[10];
    const float* ab1 = (const float*)d_in[11];
    const float* aw2 = (const float*)d_in[12];
    const float* ab2 = (const float*)d_in[13];
    const float* aw3 = (const float*)d_in[14];
    const float* ab3 = (const float*)d_in[15];
    float* out = (float*)d_out;

    static int attr_set = 0;
    if (!attr_set) {
        cudaFuncSetAttribute(k_hyper_mma, cudaFuncAttributeMaxDynamicSharedMemorySize, HSMEM);
        cudaFuncSetAttribute(k_tail_mma, cudaFuncAttributeMaxDynamicSharedMemorySize, TSMEM);
        attr_set = 1;
    }

    k_prep<<<1064, 256>>>(obs, lat, hw1, hb1, hw2, vw1, vw2, aw1, aw2);  // 0
    k_hyper_mma<<<512, 256, HSMEM>>>(hb2);                               // 1
    k_combine_mean<<<BATCH, 256>>>();                                    // 2
    k_tail_mma<<<128, 512, TSMEM>>>(vb1, vb2, ab1, ab2, aw3, ab3);       // 3
    k_final<<<BATCH, HID>>>(out);                                        // 4
}

// round 14
// speedup vs baseline: 1.0431x; 1.0104x over previous
#include <cuda_runtime.h>
#include <cuda_fp16.h>
#include <math.h>
#include <stdint.h>

// Problem constants
#define NTOT 8192   // B * A
#define BATCH 512
#define NADV 16
#define DIN 64      // DS + DO
#define HID 128

// Scratch
__device__ float g_x[NTOT * DIN];
__device__ float g_embp[2 * NTOT * HID];   // partial einsum sums (pre-tanh), 2 d-halves
__device__ float g_vals[NTOT * HID];
__device__ float g_sc[NTOT];
// Hyper A tiles: fp16 hi only, pitch 272B; 128-row tile = 34816B = 2176 uint4
__device__ uint4 g_abf[64 * 2176];
// Tail tiles: fp16 hi/lo, pitch 528B; 128-row tile = 67584B = 4224 uint4
__device__ uint4 g_ebf[64 * 4224];   // emb tiles (tail A)
__device__ uint4 g_mbf[4 * 4224];    // mean tiles
__device__ uint4 g_wbf[5 * 4224];    // tail weights: vw1,vw2,aw1a,aw1b,aw2 ([k][n])
// Hyper B tiles: fp16 hi only, pitch 272B; tile = 34816B = 2176 uint4
__device__ uint4 g_bbf[64 * 2176];

// ---------------------------------------------------------------------------
// helpers
// ---------------------------------------------------------------------------
__device__ __forceinline__ uint32_t smem_u32(const void* p) {
    uint32_t a;
    asm("{ .reg .u64 t; cvta.to.shared.u64 t, %1; cvt.u32.u64 %0, t; }" : "=r"(a) : "l"(p));
    return a;
}
__device__ __forceinline__ void f2hl16(float v, uint16_t& h, uint16_t& l) {
    __half hh = __float2half_rn(v);
    float r = v - __half2float(hh);
    __half hl = __float2half_rn(r);
    h = __half_as_ushort(hh);
    l = __half_as_ushort(hl);
}
__device__ __forceinline__ void pack_hl2(float v0, float v1, uint32_t& hi, uint32_t& lo) {
    uint16_t h0, l0, h1, l1;
    f2hl16(v0, h0, l0);
    f2hl16(v1, h1, l1);
    hi = (uint32_t)h0 | ((uint32_t)h1 << 16);
    lo = (uint32_t)l0 | ((uint32_t)l1 << 16);
}
__device__ __forceinline__ uint32_t pack_h2(float v0, float v1) {
    return (uint32_t)__half_as_ushort(__float2half_rn(v0)) |
           ((uint32_t)__half_as_ushort(__float2half_rn(v1)) << 16);
}
__device__ __forceinline__ void ldsm_x4(uint32_t* r, uint32_t addr) {
    asm volatile("ldmatrix.sync.aligned.m8n8.x4.shared.b16 {%0,%1,%2,%3}, [%4];"
                 : "=r"(r[0]), "=r"(r[1]), "=r"(r[2]), "=r"(r[3]) : "r"(addr));
}
__device__ __forceinline__ void ldsm_x4_t(uint32_t* r, uint32_t addr) {
    asm volatile("ldmatrix.sync.aligned.m8n8.x4.trans.shared.b16 {%0,%1,%2,%3}, [%4];"
                 : "=r"(r[0]), "=r"(r[1]), "=r"(r[2]), "=r"(r[3]) : "r"(addr));
}
__device__ __forceinline__ void mma16816h(float* d, const uint32_t* a, uint32_t b0, uint32_t b1) {
    asm volatile(
        "mma.sync.aligned.m16n8k16.row.col.f32.f16.f16.f32 "
        "{%0,%1,%2,%3}, {%4,%5,%6,%7}, {%8,%9}, {%0,%1,%2,%3};"
        : "+f"(d[0]), "+f"(d[1]), "+f"(d[2]), "+f"(d[3])
        : "r"(a[0]), "r"(a[1]), "r"(a[2]), "r"(a[3]), "r"(b0), "r"(b1));
}
__device__ __forceinline__ void cp16(uint32_t dst, const void* src) {
    asm volatile("cp.async.cg.shared.global [%0], [%1], 16;" :: "r"(dst), "l"(src) : "memory");
}
#define CP_COMMIT() asm volatile("cp.async.commit_group;" ::: "memory")
#define CP_WAIT(N)  asm volatile("cp.async.wait_group %0;" :: "n"(N) : "memory")

// ---------------------------------------------------------------------------
// Kernel 0 (fused prep): blocks 0..511 h1 -> A tiles + g_x;
//   512..1023: hw2 -> B tiles;  1024..1063: tail weights -> g_wbf
// ---------------------------------------------------------------------------
__global__ __launch_bounds__(256) void k_prep(
    const float* __restrict__ obs, const float* __restrict__ lat,
    const float* __restrict__ hw1, const float* __restrict__ hb1,
    const float* __restrict__ hw2,
    const float* __restrict__ vw1, const float* __restrict__ vw2,
    const float* __restrict__ aw1, const float* __restrict__ aw2) {
    int tid = threadIdx.x;
    if (blockIdx.x >= 1024) {
        int idx = (blockIdx.x - 1024) * 256 + tid;  // 10240
        int t = idx >> 11, rem = idx & 2047;
        int k = rem >> 4, c = rem & 15;
        const float* W = (t == 0) ? vw1 : (t == 1) ? vw2 : (t == 2) ? aw1
                         : (t == 3) ? (aw1 + 16384) : aw2;
        uint32_t hi[4], lo[4];
#pragma unroll
        for (int j = 0; j < 4; j++) {
            float2 v = *(const float2*)(W + k * 128 + c * 8 + 2 * j);
            pack_hl2(v.x, v.y, hi[j], lo[j]);
        }
        uint8_t* base = (uint8_t*)g_wbf + t * 67584 + k * 528;
        *(uint4*)(base + c * 16) = make_uint4(hi[0], hi[1], hi[2], hi[3]);
        *(uint4*)(base + 256 + c * 16) = make_uint4(lo[0], lo[1], lo[2], lo[3]);
        return;
    }
    if (blockIdx.x >= 512) {
        int idx = (blockIdx.x - 512) * 256 + tid;   // 131072
        int n = idx & 127, kc = (idx >> 7) & 15, d = idx >> 11;
        int k0 = kc * 8;
        uint32_t hv[4];
#pragma unroll
        for (int j = 0; j < 4; j++) {
            float v0 = hw2[(k0 + 2 * j) * 8192 + d * 128 + n];
            float v1 = hw2[(k0 + 2 * j + 1) * 8192 + d * 128 + n];
            hv[j] = pack_h2(v0, v1);
        }
        uint8_t* base = (uint8_t*)g_bbf + d * 34816 + n * 272;
        *(uint4*)(base + k0 * 2) = make_uint4(hv[0], hv[1], hv[2], hv[3]);
        return;
    }
    // ---- build h1 ----
    __shared__ __align__(16) float sw[DIN][HID];
    __shared__ float sb[HID];
    __shared__ float sx[16][DIN];
    int n0 = blockIdx.x * 16;

    for (int i = tid; i < DIN * HID; i += 256) ((float*)sw)[i] = hw1[i];
    if (tid < HID) sb[tid] = hb1[tid];
    for (int i = tid; i < 16 * DIN; i += 256) {
        int r = i >> 6, d = i & 63;
        int n = n0 + r;
        float v = (d < 32) ? obs[(n & 511) * 32 + d] : lat[n * 32 + (d - 32)];
        sx[r][d] = v;
        g_x[n * DIN + d] = v;
    }
    __syncthreads();

    int r = tid >> 4, cg = tid & 15;
    float acc[8];
#pragma unroll
    for (int c = 0; c < 8; c++) acc[c] = 0.f;
#pragma unroll 8
    for (int d = 0; d < DIN; d++) {
        float a = sx[r][d];
        float4 w0 = *(const float4*)&sw[d][cg * 8];
        float4 w1 = *(const float4*)&sw[d][cg * 8 + 4];
        acc[0] += a * w0.x; acc[1] += a * w0.y;
        acc[2] += a * w0.z; acc[3] += a * w0.w;
        acc[4] += a * w1.x; acc[5] += a * w1.y;
        acc[6] += a * w1.z; acc[7] += a * w1.w;
    }
    int n = n0 + r;
    uint32_t hv[4];
#pragma unroll
    for (int j = 0; j < 4; j++)
        hv[j] = pack_h2(fmaxf(acc[2 * j] + sb[cg * 8 + 2 * j], 0.f),
                        fmaxf(acc[2 * j + 1] + sb[cg * 8 + 2 * j + 1], 0.f));
    uint8_t* base = (uint8_t*)g_abf + (n >> 7) * 34816 + (n & 127) * 272;
    *(uint4*)(base + cg * 16) = make_uint4(hv[0], hv[1], hv[2], hv[3]);
}

// ---------------------------------------------------------------------------
// Kernel 1: HMMA hypernet, 1-pass fp16 (R11 geometry + single-sync pipeline).
// 256 CTAs x 256 thr (2 CTAs/SM). CTA = 64-row block x 32-d half.
// 8 warps = 2m x 4n, warp tile m32 x n32.
// smem: sA 17408 | SX 8448 | bias 1024 | B dbl 2x34816 = 96512
// ---------------------------------------------------------------------------
#define SA_OFF    0
#define SX_OFF    17408
#define SBIAS_OFF 25856
#define SB_OFF    26880
#define SB_TILE   34816
#define HSMEM     96512

__global__ __launch_bounds__(256, 2) void k_hyper_mma(const float* __restrict__ hb2) {
    extern __shared__ __align__(128) uint8_t smem[];
    const uint32_t sbase = smem_u32(smem);
    int tid = threadIdx.x, wid = tid >> 5, lane = tid & 31;
    int rb = blockIdx.x >> 1, dh = blockIdx.x & 1;   // rb 0..127 (64-row), dh 0..1
    int n0 = rb * 64, d0 = dh * 32;
    int wm = wid & 1, wn = wid >> 1;                 // 2m x 4n; warp tile 32x32

    // Prologue: A tile + B(0) + bias(0) in one group
    {
        const uint4* asrc = &g_abf[(rb >> 1) * 2176 + (rb & 1) * 1088];
        for (int j = tid; j < 1088; j += 256) cp16(sbase + SA_OFF + j * 16, asrc + j);
        const uint4* bsrc = &g_bbf[d0 * 2176];
        for (int j = tid; j < 2176; j += 256) cp16(sbase + SB_OFF + j * 16, bsrc + j);
        if (tid < 32) cp16(sbase + SBIAS_OFF + tid * 16, (const uint4*)(hb2 + d0 * 128) + tid);
        CP_COMMIT();
    }
    float* SX = (float*)(smem + SX_OFF);   // [64][33]
    for (int i = tid; i < 64 * 32; i += 256) {
        int r = i >> 5, d = i & 31;
        SX[r * 33 + d] = g_x[(n0 + r) * 64 + d0 + d];
    }

    const int a_r = (lane & 15);
    const int a_kadd = (lane >> 4) * 8;
    const int bm = lane >> 3;
    const int b_n = ((bm >> 1) << 3) + (lane & 7);
    const int b_kadd = (bm & 1) * 8;
    const int r_q = lane >> 2;
    const int c_q = (lane & 3) * 2;

    float emb[2][4][4];
#pragma unroll
    for (int mt = 0; mt < 2; mt++)
#pragma unroll
        for (int t = 0; t < 4; t++)
#pragma unroll
            for (int c = 0; c < 4; c++) emb[mt][t][c] = 0.f;

    for (int i = 0; i < 32; i++) {
        int b = i & 1;
        // Single-sync pipeline: buffer b is ready; everyone finished reading 1-b.
        CP_WAIT(0);
        __syncthreads();
        if (i < 31) {
            const uint4* src = &g_bbf[(d0 + i + 1) * 2176];
            uint32_t dst = sbase + SB_OFF + (1 - b) * SB_TILE;
            for (int j = tid; j < 2176; j += 256) cp16(dst + j * 16, src + j);
            if (tid < 32)
                cp16(sbase + SBIAS_OFF + (1 - b) * 512 + tid * 16,
                     (const uint4*)(hb2 + (d0 + i + 1) * 128) + tid);
            CP_COMMIT();
        }

        const uint32_t Ab = sbase + SA_OFF;
        const uint32_t Bb = sbase + SB_OFF + b * SB_TILE;
        float S[2][4][4];
#pragma unroll
        for (int mt = 0; mt < 2; mt++)
#pragma unroll
            for (int t = 0; t < 4; t++)
#pragma unroll
                for (int c = 0; c < 4; c++) S[mt][t][c] = 0.f;

#pragma unroll
        for (int ks = 0; ks < 8; ks++) {
            uint32_t ah[2][4], bh[2][4];
            int ka = ks * 16 + a_kadd;
#pragma unroll
            for (int mt = 0; mt < 2; mt++) {
                int ar = wm * 32 + mt * 16 + a_r;
                ldsm_x4(ah[mt], Ab + ar * 272 + ka * 2);
            }
            int kb = ks * 16 + b_kadd;
#pragma unroll
            for (int nt = 0; nt < 2; nt++) {
                int nr = wn * 32 + nt * 16 + b_n;
                ldsm_x4(bh[nt], Bb + nr * 272 + kb * 2);
            }
#pragma unroll
            for (int mt = 0; mt < 2; mt++)
#pragma unroll
                for (int nt = 0; nt < 2; nt++) {
                    mma16816h(S[mt][nt * 2], ah[mt], bh[nt][0], bh[nt][1]);
                    mma16816h(S[mt][nt * 2 + 1], ah[mt], bh[nt][2], bh[nt][3]);
                }
        }
        const float* bias = (const float*)(smem + SBIAS_OFF) + b * 128;
#pragma unroll
        for (int mt = 0; mt < 2; mt++) {
            int rbase = wm * 32 + mt * 16 + r_q;
            float xlo = SX[rbase * 33 + i];
            float xhi = SX[(rbase + 8) * 33 + i];
#pragma unroll
            for (int t = 0; t < 4; t++) {
                int col = wn * 32 + t * 8 + c_q;
                float2 bv = *(const float2*)&bias[col];
                float* e = emb[mt][t];
                e[0] += xlo * fmaxf(S[mt][t][0] + bv.x, 0.f);
                e[1] += xlo * fmaxf(S[mt][t][1] + bv.y, 0.f);
                e[2] += xhi * fmaxf(S[mt][t][2] + bv.x, 0.f);
                e[3] += xhi * fmaxf(S[mt][t][3] + bv.y, 0.f);
            }
        }
    }

    float* dst = g_embp + dh * (NTOT * HID) + n0 * 128;
#pragma unroll
    for (int mt = 0; mt < 2; mt++) {
        int row = wm * 32 + mt * 16 + r_q;
#pragma unroll
        for (int t = 0; t < 4; t++) {
            int col = wn * 32 + t * 8 + c_q;
            *(float2*)&dst[row * 128 + col] = make_float2(emb[mt][t][0], emb[mt][t][1]);
            *(float2*)&dst[(row + 8) * 128 + col] = make_float2(emb[mt][t][2], emb[mt][t][3]);
        }
    }
}

// ---------------------------------------------------------------------------
// Kernel 2: combine 2 partials (tanh) -> fp16 hi/lo emb tiles + mean tiles.
// ---------------------------------------------------------------------------
__global__ __launch_bounds__(256) void k_combine_mean() {
    __shared__ float2 red[4][64];
    int b = blockIdx.x, tid = threadIdx.x;
    int c2 = tid & 63, rg = tid >> 6;
    uint8_t* ebase = (uint8_t*)g_ebf + (b >> 3) * 67584 + ((b & 7) * 16) * 528;
    float2 sum = make_float2(0.f, 0.f);
#pragma unroll
    for (int r = 0; r < 4; r++) {
        int row = rg * 4 + r;
        int n = b * 16 + row;
        float2 p0 = *(const float2*)&g_embp[n * 128 + 2 * c2];
        float2 p1 = *(const float2*)&g_embp[NTOT * HID + n * 128 + 2 * c2];
        float v0 = tanhf(p0.x + p1.x), v1 = tanhf(p0.y + p1.y);
        sum.x += v0;
        sum.y += v1;
        uint32_t hi, lo;
        pack_hl2(v0, v1, hi, lo);
        *(uint32_t*)(ebase + row * 528 + c2 * 4) = hi;
        *(uint32_t*)(ebase + row * 528 + 256 + c2 * 4) = lo;
    }
    red[rg][c2] = sum;
    __syncthreads();
    if (rg == 0) {
        float2 m;
        m.x = (red[0][c2].x + red[1][c2].x + red[2][c2].x + red[3][c2].x) * (1.f / 16.f);
        m.y = (red[0][c2].y + red[1][c2].y + red[2][c2].y + red[3][c2].y) * (1.f / 16.f);
        uint32_t hi, lo;
        pack_hl2(m.x, m.y, hi, lo);
        uint8_t* mbase = (uint8_t*)g_mbf + (b >> 7) * 67584 + (b & 127) * 528;
        *(uint32_t*)(mbase + c2 * 4) = hi;
        *(uint32_t*)(mbase + 256 + c2 * 4) = lo;
    }
}

// ---------------------------------------------------------------------------
// Kernel 3: pipelined HMMA tail (3-pass, unchanged).
// ---------------------------------------------------------------------------
#define TA_OFF  0
#define TW0_OFF 67584
#define TW1_OFF 135168
#define TB_OFF  202752
#define T3_OFF  203776
#define TSMEM   204288

__device__ __forceinline__ void t_layer(uint32_t sbase, uint32_t Wb, int wm, int wn, int lane,
                                        float S[2][4][4]) {
    const int a_r = lane & 15, a_kadd = (lane >> 4) * 8;
    const int b_krow = lane & 15, b_nadd = (lane >> 4) * 8;
    const uint32_t Ab = sbase + TA_OFF;
#pragma unroll
    for (int ks = 0; ks < 8; ks++) {
        uint32_t ah[2][4], al[2][4], wh[2][4], wl[2][4];
        int ka = ks * 16 + a_kadd;
#pragma unroll
        for (int mt = 0; mt < 2; mt++) {
            int ar = wm * 32 + mt * 16 + a_r;
            ldsm_x4(ah[mt], Ab + ar * 528 + ka * 2);
            ldsm_x4(al[mt], Ab + ar * 528 + 256 + ka * 2);
        }
#pragma unroll
        for (int nt = 0; nt < 2; nt++) {
            uint32_t base = Wb + (ks * 16 + b_krow) * 528 + (wn * 32 + nt * 16 + b_nadd) * 2;
            ldsm_x4_t(wh[nt], base);
            ldsm_x4_t(wl[nt], base + 256);
        }
#pragma unroll
        for (int mt = 0; mt < 2; mt++)
#pragma unroll
            for (int nt = 0; nt < 2; nt++) {
                mma16816h(S[mt][nt * 2], ah[mt], wh[nt][0], wh[nt][1]);
                mma16816h(S[mt][nt * 2], al[mt], wh[nt][0], wh[nt][1]);
                mma16816h(S[mt][nt * 2], ah[mt], wl[nt][0], wl[nt][1]);
                mma16816h(S[mt][nt * 2 + 1], ah[mt], wh[nt][2], wh[nt][3]);
                mma16816h(S[mt][nt * 2 + 1], al[mt], wh[nt][2], wh[nt][3]);
                mma16816h(S[mt][nt * 2 + 1], ah[mt], wl[nt][2], wl[nt][3]);
            }
    }
}
__device__ __forceinline__ void t_act_to_sA(uint8_t* smem, const float* bias,
                                            int wm, int wn, int lane, float S[2][4][4]) {
    int r_q = lane >> 2, c_q = (lane & 3) * 2;
#pragma unroll
    for (int mt = 0; mt < 2; mt++) {
        int row = wm * 32 + mt * 16 + r_q;
#pragma unroll
        for (int t = 0; t < 4; t++) {
            int col = wn * 32 + t * 8 + c_q;
            float2 bv = *(const float2*)&bias[col];
            uint32_t hi, lo;
            pack_hl2(fmaxf(S[mt][t][0] + bv.x, 0.f), fmaxf(S[mt][t][1] + bv.y, 0.f), hi, lo);
            *(uint32_t*)(smem + TA_OFF + row * 528 + col * 2) = hi;
            *(uint32_t*)(smem + TA_OFF + row * 528 + 256 + col * 2) = lo;
            pack_hl2(fmaxf(S[mt][t][2] + bv.x, 0.f), fmaxf(S[mt][t][3] + bv.y, 0.f), hi, lo);
            *(uint32_t*)(smem + TA_OFF + (row + 8) * 528 + col * 2) = hi;
            *(uint32_t*)(smem + TA_OFF + (row + 8) * 528 + 256 + col * 2) = lo;
        }
    }
}

__global__ __launch_bounds__(512, 1) void k_tail_mma(
    const float* __restrict__ vb1, const float* __restrict__ vb2,
    const float* __restrict__ ab1, const float* __restrict__ ab2,
    const float* __restrict__ aw3, const float* __restrict__ ab3) {
    extern __shared__ __align__(128) uint8_t smem[];
    const uint32_t sbase = smem_u32(smem);
    int tid = threadIdx.x, wid = tid >> 5, lane = tid & 31;
    int wm = wid & 3, wn = wid >> 2;
    int r_q = lane >> 2, c_q = (lane & 3) * 2;
    float* b0 = (float*)(smem + TB_OFF);
    float* b1 = b0 + 128;

    float S[2][4][4];
#define ZERO_S() { _Pragma("unroll") for (int mt = 0; mt < 2; mt++) \
    _Pragma("unroll") for (int t = 0; t < 4; t++) \
    _Pragma("unroll") for (int c = 0; c < 4; c++) S[mt][t][c] = 0.f; }

    if (blockIdx.x < 64) {
        int n0 = blockIdx.x * 128;
        for (int j = tid; j < 4224; j += 512) cp16(sbase + TA_OFF + j * 16, &g_ebf[blockIdx.x * 4224 + j]);
        for (int j = tid; j < 4224; j += 512) cp16(sbase + TW0_OFF + j * 16, &g_wbf[0 * 4224 + j]);
        CP_COMMIT();
        for (int j = tid; j < 4224; j += 512) cp16(sbase + TW1_OFF + j * 16, &g_wbf[1 * 4224 + j]);
        CP_COMMIT();
        if (tid < 128) b0[tid] = vb1[tid];
        else if (tid < 256) b1[tid - 128] = vb2[tid - 128];
        CP_WAIT(1);
        __syncthreads();
        ZERO_S();
        t_layer(sbase, sbase + TW0_OFF, wm, wn, lane, S);
        __syncthreads();
        t_act_to_sA(smem, b0, wm, wn, lane, S);
        CP_WAIT(0);
        __syncthreads();
        ZERO_S();
        t_layer(sbase, sbase + TW1_OFF, wm, wn, lane, S);
#pragma unroll
        for (int mt = 0; mt < 2; mt++) {
            int row = wm * 32 + mt * 16 + r_q;
#pragma unroll
            for (int t = 0; t < 4; t++) {
                int col = wn * 32 + t * 8 + c_q;
                float2 bv = *(const float2*)&b1[col];
                *(float2*)&g_vals[(n0 + row) * 128 + col] =
                    make_float2(fmaxf(S[mt][t][0] + bv.x, 0.f), fmaxf(S[mt][t][1] + bv.y, 0.f));
                *(float2*)&g_vals[(n0 + row + 8) * 128 + col] =
                    make_float2(fmaxf(S[mt][t][2] + bv.x, 0.f), fmaxf(S[mt][t][3] + bv.y, 0.f));
            }
        }
    } else {
        int cb = blockIdx.x - 64;
        int n0 = cb * 128;
        for (int j = tid; j < 4224; j += 512) cp16(sbase + TA_OFF + j * 16, &g_ebf[cb * 4224 + j]);
        for (int j = tid; j < 4224; j += 512) cp16(sbase + TW0_OFF + j * 16, &g_wbf[2 * 4224 + j]);
        CP_COMMIT();
        for (int j = tid; j < 4224; j += 512) cp16(sbase + TW1_OFF + j * 16, &g_wbf[3 * 4224 + j]);
        CP_COMMIT();
        if (tid < 128) b0[tid] = ab1[tid];
        else if (tid < 256) b1[tid - 128] = ab2[tid - 128];
        else if (tid < 384) ((float*)(smem + T3_OFF))[tid - 256] = aw3[tid - 256];
        CP_WAIT(1);
        __syncthreads();
        ZERO_S();
        t_layer(sbase, sbase + TW0_OFF, wm, wn, lane, S);  // layer1a
        __syncthreads();
        for (int j = tid; j < 4224; j += 512) cp16(sbase + TA_OFF + j * 16, &g_mbf[(cb & 3) * 4224 + j]);
        CP_COMMIT();
        for (int j = tid; j < 4224; j += 512) cp16(sbase + TW0_OFF + j * 16, &g_wbf[4 * 4224 + j]);
        CP_COMMIT();
        CP_WAIT(1);
        __syncthreads();
        t_layer(sbase, sbase + TW1_OFF, wm, wn, lane, S);  // layer1b
        __syncthreads();
        t_act_to_sA(smem, b0, wm, wn, lane, S);
        CP_WAIT(0);
        __syncthreads();
        ZERO_S();
        t_layer(sbase, sbase + TW0_OFF, wm, wn, lane, S);  // layer2
        __syncthreads();
        t_act_to_sA(smem, b1, wm, wn, lane, S);
        __syncthreads();
        const float* sw3 = (const float*)(smem + T3_OFF);
        int row = tid >> 2, l4 = tid & 3;
        float s = 0.f;
#pragma unroll
        for (int j = 0; j < 32; j++) {
            int k = l4 * 32 + j;
            float hi = __half2float(*(const __half*)(smem + TA_OFF + row * 528 + k * 2));
            float lo = __half2float(*(const __half*)(smem + TA_OFF + row * 528 + 256 + k * 2));
            s += (hi + lo) * sw3[k];
        }
        s += __shfl_xor_sync(0xffffffffu, s, 1);
        s += __shfl_xor_sync(0xffffffffu, s, 2);
        if (l4 == 0) g_sc[n0 + row] = s + ab3[0];
    }
}

// ---------------------------------------------------------------------------
// Kernel 4: softmax over 16 + weighted sum -> out[512,128]
// ---------------------------------------------------------------------------
__global__ void k_final(float* __restrict__ out) {
    __shared__ float sc[NADV];
    int b = blockIdx.x, tid = threadIdx.x;
    if (tid < NADV) sc[tid] = g_sc[b * NADV + tid];
    __syncthreads();
    float m = sc[0];
#pragma unroll
    for (int a = 1; a < NADV; a++) m = fmaxf(m, sc[a]);
    float den = 0.f, o = 0.f;
#pragma unroll
    for (int a = 0; a < NADV; a++) {
        float e = expf(sc[a] - m);
        den += e;
        o += e * g_vals[(b * NADV + a) * HID + tid];
    }
    out[b * HID + tid] = o / den;
}

// ---------------------------------------------------------------------------
extern "C" void kernel_launch(void* const* d_in, const int* in_sizes, int n_in,
                              void* d_out, int out_size) {
    const float* obs = (const float*)d_in[0];
    const float* lat = (const float*)d_in[1];
    const float* hw1 = (const float*)d_in[2];
    const float* hb1 = (const float*)d_in[3];
    const float* hw2 = (const float*)d_in[4];
    const float* hb2 = (const float*)d_in[5];
    const float* vw1 = (const float*)d_in[6];
    const float* vb1 = (const float*)d_in[7];
    const float* vw2 = (const float*)d_in[8];
    const float* vb2 = (const float*)d_in[9];
    const float* aw1 = (const float*)d_in[10];
    const float* ab1 = (const float*)d_in[11];
    const float* aw2 = (const float*)d_in[12];
    const float* ab2 = (const float*)d_in[13];
    const float* aw3 = (const float*)d_in[14];
    const float* ab3 = (const float*)d_in[15];
    float* out = (float*)d_out;

    static int attr_set = 0;
    if (!attr_set) {
        cudaFuncSetAttribute(k_hyper_mma, cudaFuncAttributeMaxDynamicSharedMemorySize, HSMEM);
        cudaFuncSetAttribute(k_tail_mma, cudaFuncAttributeMaxDynamicSharedMemorySize, TSMEM);
        attr_set = 1;
    }

    k_prep<<<1064, 256>>>(obs, lat, hw1, hb1, hw2, vw1, vw2, aw1, aw2);  // 0
    k_hyper_mma<<<256, 256, HSMEM>>>(hb2);                               // 1
    k_combine_mean<<<BATCH, 256>>>();                                    // 2
    k_tail_mma<<<128, 512, TSMEM>>>(vb1, vb2, ab1, ab2, aw3, ab3);       // 3
    k_final<<<BATCH, HID>>>(out);                                        // 4
}